// round 5
// baseline (speedup 1.0000x reference)
#include <cuda_runtime.h>
#include <stdint.h>

// ---------------------------------------------------------------------------
// FasterRCNN RPN proposal head, round 5: TWO launches.
//  Launch 1 (persistent, grid = 4 blocks/SM, software grid barriers):
//    zero -> stream (hist>0.9 + warp-aggregated spill) -> cutoff -> compact ->
//    rank+decode (fused) -> IoU mask matrix
//  Launch 2: NMS via Jacobi sandwich (rem1/rem2 parallel OR passes) + exact
//    serial scan over the few ambiguous rows only (staged in smem).
// ---------------------------------------------------------------------------

#define HF 512
#define WF 512
#define KA 9
#define NANCH (HF * WF * KA)       // 2359296
#define NANCH2 (NANCH / 2)
#define IMGW 16384.0f
#define IMGH 16384.0f
#define TOPK_N 4000
#define THR 0.5f
#define IOU_T 0.3f
#define NW 63
#define NBINS 65536
#define CAP 16384
#define BITS_BASE 0x3F000000u      // bits of 0.5f
#define SPILL_S 0.9f
#define PREF_MIN_BIN 52430u
#define SPILLCAP 400000
#define RCAP 4096                  // flagged rows (<= TOPK_N, so never overflows)
#define AMAX 400                   // staged ambiguous rows (400*63*8 = 201600 B)

typedef unsigned long long ull;

// ---- scratch ---------------------------------------------------------------
__device__ uint32_t d_hist[NBINS];
__device__ uint32_t d_cutbin;
__device__ uint32_t d_count;
__device__ uint32_t d_spillcount;
__device__ int      d_fallback;
__device__ ull      d_spill[SPILLCAP];
__device__ ull      d_keys[CAP];
__device__ float d_bx1[TOPK_N], d_by1[TOPK_N], d_bx2[TOPK_N], d_by2[TOPK_N], d_ar[TOPK_N];
__device__ int   d_valid[TOPK_N];
__device__ ull   d_mask[TOPK_N * NW];
__device__ ull   d_rnz[NW];

// ---- software grid barrier -------------------------------------------------
__device__ unsigned int          g_barcnt = 0;
__device__ volatile unsigned int g_bargen = 0;

__device__ __forceinline__ void gridbar() {
    __syncthreads();
    if (threadIdx.x == 0) {
        __threadfence();
        unsigned int g = g_bargen;
        if (atomicAdd(&g_barcnt, 1u) == gridDim.x - 1) {
            g_barcnt = 0;
            __threadfence();
            g_bargen = g + 1;
        } else {
            while (g_bargen == g) __nanosleep(64);
        }
        __threadfence();
    }
    __syncthreads();
}

// p1 of 2-way softmax, bit-identical to jax.nn.softmax (max-side exp == 1.0f).
__device__ __forceinline__ float score_p1_pos(float l0, float l1) {
    float x = expf(l0 - l1);
    return 1.0f / (x + 1.0f);
}

__device__ __forceinline__ void cutoff_scan(int t) {
    __shared__ uint32_t csum[256], sfine[256];
    __shared__ int s_c;
    __shared__ uint32_t s_acc;
    int warp = t >> 5, lane = t & 31;
    for (int c = warp; c < 256; c += 8) {
        uint32_t s = 0;
        for (int b = lane; b < 256; b += 32) s += d_hist[c * 256 + b];
        #pragma unroll
        for (int o = 16; o; o >>= 1) s += __shfl_down_sync(0xFFFFFFFFu, s, o);
        if (lane == 0) csum[c] = s;
    }
    __syncthreads();
    if (t == 0) {
        uint32_t acc = 0; int c;
        for (c = 255; c >= 0; c--) {
            if (acc + csum[c] >= TOPK_N) break;
            acc += csum[c];
        }
        s_c = c; s_acc = acc;
    }
    __syncthreads();
    if (s_c >= 0) sfine[t] = d_hist[s_c * 256 + t];
    __syncthreads();
    if (t == 0) {
        uint32_t cut = 0;
        if (s_c >= 0) {
            uint32_t acc = s_acc; int b;
            for (b = 255; b >= 0; b--) {
                acc += sfine[b];
                if (acc >= TOPK_N) break;
            }
            if (b < 0) b = 0;
            cut = (uint32_t)(s_c * 256 + b);
        }
        d_cutbin = cut;
        int fb = 0;
        if (cut < PREF_MIN_BIN) fb = 1;
        if (d_spillcount > SPILLCAP) fb = 1;
        d_fallback = fb;
    }
}

__global__ void __launch_bounds__(256)
k_main(const float4* __restrict__ obj4,
       const float*  __restrict__ obj,
       const float*  __restrict__ reg,
       const float*  __restrict__ anch,
       float* __restrict__ out) {
    const int t   = threadIdx.x;
    const int tid = blockIdx.x * 256 + t;
    const int gsz = gridDim.x * 256;
    const int lane = t & 31;

    __shared__ ull s_tile[1024];
    __shared__ float s_cx1[4][64], s_cy1[4][64], s_cx2[4][64], s_cy2[4][64], s_ca[4][64];

    // ---------------- Phase Z ---------------------------------------------
    for (int i = tid; i < NBINS; i += gsz) d_hist[i] = 0u;
    for (int i = tid; i < 6 * TOPK_N; i += gsz) out[i] = 0.0f;
    for (int i = tid; i < TOPK_N; i += gsz) {
        d_valid[i] = 0;
        d_bx1[i] = 0.f; d_by1[i] = 0.f; d_bx2[i] = 0.f; d_by2[i] = 0.f; d_ar[i] = 0.f;
    }
    if (tid < NW) d_rnz[tid] = 0ull;
    if (tid == 0) { d_count = 0u; d_spillcount = 0u; d_cutbin = 0u; d_fallback = 0; }
    gridbar();

    // ---------------- Phase P1: stream, hist(s>0.9) + warp-agg spill ------
    {
        int iters = (NANCH2 + gsz - 1) / gsz;
        for (int it = 0; it < iters; it++) {
            int i2 = tid + it * gsz;
            float4 v = make_float4(0.f, 0.f, 0.f, 0.f);
            if (i2 < NANCH2) v = obj4[i2];
            #pragma unroll
            for (int h = 0; h < 2; h++) {
                bool want = false; uint32_t sb = 0;
                float l0 = h ? v.z : v.x;
                float l1 = h ? v.w : v.y;
                if (i2 < NANCH2 && l1 > l0) {
                    float s = score_p1_pos(l0, l1);
                    if (s > SPILL_S) {
                        sb = __float_as_uint(s);
                        uint32_t b = (sb - BITS_BASE) >> 7;
                        if (b > (NBINS - 1)) b = NBINS - 1;
                        atomicAdd(&d_hist[b], 1u);
                        want = true;
                    }
                }
                unsigned m = __ballot_sync(0xFFFFFFFFu, want);
                if (m) {
                    int leader = __ffs(m) - 1;
                    uint32_t base = 0;
                    if (lane == leader) base = atomicAdd(&d_spillcount, (uint32_t)__popc(m));
                    base = __shfl_sync(0xFFFFFFFFu, base, leader);
                    if (want) {
                        uint32_t pos = base + __popc(m & ((1u << lane) - 1u));
                        uint32_t idx = 2u * (uint32_t)i2 + (uint32_t)h;
                        if (pos < SPILLCAP) d_spill[pos] = ((ull)sb << 32) | (ull)(~idx);
                    }
                }
            }
        }
    }
    gridbar();

    // ---------------- Phase C: cutoff -------------------------------------
    if (blockIdx.x == 0) cutoff_scan(t);
    gridbar();

    // ---------------- Phase CP: compact ------------------------------------
    int fb = d_fallback;
    if (!fb) {
        uint32_t cut = d_cutbin;
        uint32_t n = d_spillcount; if (n > SPILLCAP) n = SPILLCAP;
        for (uint32_t i = tid; i < n; i += gsz) {
            ull key = d_spill[i];
            uint32_t sb = (uint32_t)(key >> 32);
            uint32_t b  = (sb - BITS_BASE) >> 7;
            if (b > (NBINS - 1)) b = NBINS - 1;
            if (b >= cut) {
                uint32_t p = atomicAdd(&d_count, 1u);
                if (p < CAP) d_keys[p] = key;
            }
        }
        gridbar();
    } else {
        for (int i2 = tid; i2 < NANCH2; i2 += gsz) {
            float4 v = obj4[i2];
            #pragma unroll
            for (int h = 0; h < 2; h++) {
                float l0 = h ? v.z : v.x;
                float l1 = h ? v.w : v.y;
                if (l1 > l0) {
                    float s = score_p1_pos(l0, l1);
                    if (s > THR && !(s > SPILL_S)) {
                        uint32_t sb = __float_as_uint(s);
                        uint32_t b  = (sb - BITS_BASE) >> 7;
                        if (b > (NBINS - 1)) b = NBINS - 1;
                        atomicAdd(&d_hist[b], 1u);
                    }
                }
            }
        }
        gridbar();
        if (blockIdx.x == 0) cutoff_scan(t);
        gridbar();
        uint32_t cut = d_cutbin;
        for (int i2 = tid; i2 < NANCH2; i2 += gsz) {
            float4 v = obj4[i2];
            #pragma unroll
            for (int h = 0; h < 2; h++) {
                float l0 = h ? v.z : v.x;
                float l1 = h ? v.w : v.y;
                if (l1 > l0) {
                    float s = score_p1_pos(l0, l1);
                    if (s > THR) {
                        uint32_t sb = __float_as_uint(s);
                        uint32_t b  = (sb - BITS_BASE) >> 7;
                        if (b > (NBINS - 1)) b = NBINS - 1;
                        if (b >= cut) {
                            uint32_t p = atomicAdd(&d_count, 1u);
                            uint32_t idx = 2u * (uint32_t)i2 + (uint32_t)h;
                            if (p < CAP) d_keys[p] = ((ull)sb << 32) | (ull)(~idx);
                        }
                    }
                }
            }
        }
        gridbar();
    }

    // ---------------- Phase R: rank + decode --------------------------------
    {
        uint32_t cnt = d_count; if (cnt > CAP) cnt = CAP;
        int iters = (CAP + gsz - 1) / gsz;
        for (int it = 0; it < iters; it++) {
            int i = tid + it * gsz;
            int blockbase = blockIdx.x * 256 + it * gsz;
            if (blockbase >= (int)cnt) continue;
            ull mykey = (i < (int)cnt) ? d_keys[i] : 0ull;
            int rank = 0;
            int ntiles = ((int)cnt + 1023) / 1024;
            for (int tb = 0; tb < ntiles; tb++) {
                for (int u = t; u < 1024; u += 256) {
                    int j = tb * 1024 + u;
                    s_tile[u] = (j < (int)cnt) ? d_keys[j] : 0ull;
                }
                __syncthreads();
                if (i < (int)cnt) {
                    int lim = (int)cnt - tb * 1024; if (lim > 1024) lim = 1024;
                    for (int u = 0; u < lim; u++) rank += (s_tile[u] > mykey) ? 1 : 0;
                }
                __syncthreads();
            }
            if (i < (int)cnt && rank < TOPK_N) {
                uint32_t idx = ~((uint32_t)mykey);
                float2 l = ((const float2*)obj)[idx];
                float p0, p1;
                if (l.y >= l.x) {
                    float x = expf(l.x - l.y);
                    float den = x + 1.0f;
                    p0 = x / den; p1 = 1.0f / den;
                } else {
                    float y = expf(l.y - l.x);
                    float den = 1.0f + y;
                    p0 = 1.0f / den; p1 = y / den;
                }
                float4 rg = ((const float4*)reg)[idx];
                float4 a  = ((const float4*)anch)[idx];
                float cx = (a.x + a.z * 0.5f) + rg.x * a.z;
                float cy = (a.y + a.w * 0.5f) + rg.y * a.w;
                float w  = a.z * expf(rg.z);
                float h  = a.w * expf(rg.w);
                float bx = cx - w * 0.5f;
                float by = cy - h * 0.5f;
                float x1 = fminf(fmaxf(bx, 0.f), IMGW);
                float y1 = fminf(fmaxf(by, 0.f), IMGH);
                float x2 = fminf(fmaxf(bx + w, 0.f), IMGW);
                float y2 = fminf(fmaxf(by + h, 0.f), IMGH);
                float bw = x2 - x1, bh = y2 - y1;
                out[rank * 4 + 0] = x1;
                out[rank * 4 + 1] = y1;
                out[rank * 4 + 2] = bw;
                out[rank * 4 + 3] = bh;
                out[4 * TOPK_N + rank * 2 + 0] = p0;
                out[4 * TOPK_N + rank * 2 + 1] = p1;
                d_bx1[rank] = x1;
                d_by1[rank] = y1;
                d_bx2[rank] = x1 + bw;
                d_by2[rank] = y1 + bh;
                d_ar[rank]  = bw * bh;
                d_valid[rank] = (p1 > THR) ? 1 : 0;
            }
        }
    }
    gridbar();

    // ---------------- Phase M: IoU mask matrix ------------------------------
    {
        const int sub  = t >> 6;
        const int ln   = t & 63;
        const int TT = NW * NW;
        int iters = (TT + gridDim.x * 4 - 1) / (gridDim.x * 4);
        for (int it = 0; it < iters; it++) {
            int tile = (blockIdx.x + it * gridDim.x) * 4 + sub;
            int rb = 0, cb = 0;
            bool tv = tile < TT;
            if (tv) { rb = tile / NW; cb = tile - rb * NW; }
            bool comp = tv && (cb >= rb);
            if (comp) {
                int cj = cb * 64 + ln;
                if (cj < TOPK_N) {
                    s_cx1[sub][ln] = d_bx1[cj]; s_cy1[sub][ln] = d_by1[cj];
                    s_cx2[sub][ln] = d_bx2[cj]; s_cy2[sub][ln] = d_by2[cj];
                    s_ca[sub][ln]  = d_ar[cj];
                }
            }
            __syncthreads();
            if (tv) {
                int i = rb * 64 + ln;
                if (i < TOPK_N) {
                    ull wbits = 0ull;
                    if (comp) {
                        float x1 = d_bx1[i], y1 = d_by1[i];
                        float x2 = d_bx2[i], y2 = d_by2[i], ar = d_ar[i];
                        int jmax = TOPK_N - cb * 64; if (jmax > 64) jmax = 64;
                        for (int u = 0; u < jmax; u++) {
                            int j = cb * 64 + u;
                            if (j <= i) continue;
                            float iw = fmaxf(fminf(x2, s_cx2[sub][u]) - fmaxf(x1, s_cx1[sub][u]), 0.f);
                            float ih = fmaxf(fminf(y2, s_cy2[sub][u]) - fmaxf(y1, s_cy1[sub][u]), 0.f);
                            float inter = iw * ih;
                            float iou = inter / (ar + s_ca[sub][u] - inter + 1e-8f);
                            if (iou > IOU_T) wbits |= (1ull << u);
                        }
                    }
                    d_mask[(size_t)i * NW + cb] = wbits;
                    if (wbits) atomicOr(&d_rnz[i >> 6], 1ull << (i & 63));
                }
            }
            __syncthreads();
        }
    }
}

// ---------------- NMS: Jacobi sandwich + tiny exact serial scan -------------
__global__ void k_nms(float* __restrict__ out) {
    extern __shared__ ull s_amask[];   // AMAX * NW
    __shared__ ull s_vb[NW], s_flag[NW], s_rem1[NW], s_rem2[NW], s_k1[NW], s_amb[NW], s_remv[NW];
    __shared__ int s_list[RCAP];
    __shared__ int s_alist[AMAX];
    __shared__ int s_wpref[NW + 1];
    __shared__ int s_apref[NW + 1];
    __shared__ int s_R, s_A;
    int t = threadIdx.x;  // 1024 threads

    if (t < NW) { s_flag[t] = d_rnz[t]; s_vb[t] = 0ull; s_rem1[t] = 0ull; s_rem2[t] = 0ull; }
    __syncthreads();
    for (int i = t; i < TOPK_N; i += 1024)
        if (d_valid[i]) atomicOr(&s_vb[i >> 6], 1ull << (i & 63));
    __syncthreads();
    if (t < NW) s_flag[t] &= s_vb[t];   // invalid rows can never suppress
    __syncthreads();
    if (t == 0) {
        int acc = 0;
        for (int w = 0; w < NW; w++) { s_wpref[w] = acc; acc += __popcll(s_flag[w]); }
        s_wpref[NW] = acc; s_R = acc;
    }
    __syncthreads();
    if (t < NW) {
        ull bits = s_flag[t];
        int slot = s_wpref[t];
        while (bits) {
            int b = __ffsll((long long)bits) - 1;
            bits &= bits - 1ull;
            s_list[slot++] = t * 64 + b;   // R <= TOPK_N < RCAP
        }
    }
    __syncthreads();
    const int R = s_R;

    // Pass 1: rem1 = OR of masks of ALL valid flagged rows  => keep1 subset of trueKeep
    {
        int c = t & 63, g = t >> 6;   // 16 row-groups
        if (c < NW) {
            ull a0 = 0, a1 = 0, a2 = 0, a3 = 0;
            int sl = g;
            for (; sl + 48 < R; sl += 64) {
                a0 |= d_mask[(size_t)s_list[sl]      * NW + c];
                a1 |= d_mask[(size_t)s_list[sl + 16] * NW + c];
                a2 |= d_mask[(size_t)s_list[sl + 32] * NW + c];
                a3 |= d_mask[(size_t)s_list[sl + 48] * NW + c];
            }
            for (; sl < R; sl += 16) a0 |= d_mask[(size_t)s_list[sl] * NW + c];
            ull acc = a0 | a1 | a2 | a3;
            if (acc) atomicOr(&s_rem1[c], acc);
        }
    }
    __syncthreads();
    if (t < NW) s_k1[t] = s_vb[t] & ~s_rem1[t];
    __syncthreads();

    // Pass 2: rem2 = OR of masks of keep1 flagged rows  => definite suppressions
    {
        int c = t & 63, g = t >> 6;
        if (c < NW) {
            ull acc = 0;
            for (int sl = g; sl < R; sl += 16) {
                int i = s_list[sl];
                if ((s_k1[i >> 6] >> (i & 63)) & 1ull)
                    acc |= d_mask[(size_t)i * NW + c];
            }
            if (acc) atomicOr(&s_rem2[c], acc);
        }
    }
    __syncthreads();
    // ambiguous flagged rows: suppressed under rem1, not under rem2
    if (t < NW) s_amb[t] = s_flag[t] & s_rem1[t] & ~s_rem2[t];
    __syncthreads();
    if (t == 0) {
        int acc = 0;
        for (int w = 0; w < NW; w++) { s_apref[w] = acc; acc += __popcll(s_amb[w]); }
        s_apref[NW] = acc; s_A = acc;
    }
    __syncthreads();
    if (t < NW) {
        ull bits = s_amb[t];
        int slot = s_apref[t];
        while (bits) {
            int b = __ffsll((long long)bits) - 1;
            bits &= bits - 1ull;
            if (slot < AMAX) s_alist[slot] = t * 64 + b;
            slot++;
        }
    }
    __syncthreads();
    int Ac = s_A < AMAX ? s_A : AMAX;
    for (int e = t; e < Ac * NW; e += 1024) {
        int sl = e / NW, c = e - sl * NW;
        s_amask[e] = d_mask[(size_t)s_alist[sl] * NW + c];
    }
    __syncthreads();

    // Exact serial resolution over ambiguous rows only.
    if (t < 32) {
        int l = t;
        ull r0 = s_rem1 ? s_rem2[l] : 0ull;          // init with definite suppressions
        ull r1 = (l + 32 < NW) ? s_rem2[l + 32] : 0ull;
        for (int w = 0; w < NW; w++) {
            if (!s_amb[w]) continue;
            ull v0 = __shfl_sync(0xFFFFFFFFu, r0, w & 31);
            ull v1 = __shfl_sync(0xFFFFFFFFu, r1, w & 31);
            ull remw = (w < 32) ? v0 : v1;
            ull act = s_amb[w] & ~remw;
            while (act) {
                int b = __ffsll((long long)act) - 1;
                act &= act - 1ull;
                int slot = s_apref[w] + __popcll(s_amb[w] & ((1ull << b) - 1ull));
                const ull* src = (slot < AMAX)
                    ? &s_amask[(size_t)slot * NW]
                    : &d_mask[(size_t)(w * 64 + b) * NW];
                r0 |= src[l];
                if (l + 32 < NW) r1 |= src[l + 32];
                act &= ~src[w];
            }
        }
        s_remv[l] = r0;
        if (l + 32 < NW) s_remv[l + 32] = r1;
    }
    __syncthreads();
    for (int i = t; i < TOPK_N; i += 1024) {
        bool kp = ((s_vb[i >> 6] >> (i & 63)) & 1ull) &&
                  !((s_remv[i >> 6] >> (i & 63)) & 1ull);
        out[6 * TOPK_N + i] = kp ? 1.0f : 0.0f;
    }
}

extern "C" void kernel_launch(void* const* d_in, const int* in_sizes, int n_in,
                              void* d_out, int out_size) {
    (void)in_sizes; (void)n_in; (void)out_size;
    const float* obj  = (const float*)d_in[0];
    const float* reg  = (const float*)d_in[1];
    const float* anch = (const float*)d_in[2];
    float* out = (float*)d_out;

    int dev = 0, sms = 0, bpm = 0;
    cudaGetDevice(&dev);
    cudaDeviceGetAttribute(&sms, cudaDevAttrMultiProcessorCount, dev);
    cudaOccupancyMaxActiveBlocksPerMultiprocessor(&bpm, k_main, 256, 0);
    if (bpm < 1) bpm = 1;
    if (bpm > 4) bpm = 4;           // cap: keeps gridbar cheap
    int grid = sms * bpm;
    if (grid < 1) grid = 1;

    const int NMS_SMEM = AMAX * NW * (int)sizeof(ull);  // 201600
    cudaFuncSetAttribute(k_nms, cudaFuncAttributeMaxDynamicSharedMemorySize, NMS_SMEM);

    k_main<<<grid, 256>>>((const float4*)obj, obj, reg, anch, out);
    k_nms <<<1, 1024, NMS_SMEM>>>(out);
}

// round 6
// speedup vs baseline: 1.1444x; 1.1444x over previous
#include <cuda_runtime.h>
#include <stdint.h>

// ---------------------------------------------------------------------------
// FasterRCNN RPN proposal head, round 6: discrete kernels (each phase at its
// own grid size), NMS via distributed Jacobi sandwich:
//   k_zero -> k_pass1 (stream: full hist + spill s>0.9)
//   -> k_cutoff -> k_compact (spill fast path / full-rescan fallback)
//   -> k_rankgather (exact rank-by-counting + box decode, fused)
//   -> k_mask (IoU bitmask; rem1 = OR of valid rows' masks, fused for free)
//   -> k_rem2 (63 blocks: rem2[c] = OR of keep1-row masks, parallel)
//   -> k_final (serial scan over ambiguous rows only; writes keep)
// ---------------------------------------------------------------------------

#define HF 512
#define WF 512
#define KA 9
#define NANCH (HF * WF * KA)       // 2359296
#define NANCH2 (NANCH / 2)
#define IMGW 16384.0f
#define IMGH 16384.0f
#define TOPK_N 4000
#define THR 0.5f
#define IOU_T 0.3f
#define NW 63
#define NBINS 65536
#define CAP 16384
#define BITS_BASE 0x3F000000u      // bits of 0.5f
#define SPILL_S 0.9f
#define PREF_MIN_BIN 52430u
#define SPILLCAP 400000
#define AMAX 400                   // staged ambiguous rows (400*63*8 = 201600 B)

typedef unsigned long long ull;

// ---- scratch ---------------------------------------------------------------
__device__ uint32_t d_hist[NBINS];
__device__ uint32_t d_cutbin;
__device__ uint32_t d_count;
__device__ uint32_t d_spillcount;
__device__ int      d_fallback;
__device__ ull      d_spill[SPILLCAP];
__device__ ull      d_keys[CAP];
__device__ float d_bx1[TOPK_N], d_by1[TOPK_N], d_bx2[TOPK_N], d_by2[TOPK_N], d_ar[TOPK_N];
__device__ int   d_valid[TOPK_N];
__device__ ull   d_vbw[NW];        // valid bits, packed
__device__ ull   d_mask[TOPK_N * NW];
__device__ ull   d_rnz[NW];        // rows (valid) with any suppression bit
__device__ ull   d_rem1[NW];       // OR of masks of ALL valid rows
__device__ ull   d_rem2[NW];       // OR of masks of keep1 rows

// p1 of 2-way softmax, bit-identical to jax.nn.softmax (max-side exp == 1.0f).
__device__ __forceinline__ float score_p1_pos(float l0, float l1) {
    float x = expf(l0 - l1);
    return 1.0f / (x + 1.0f);
}

__global__ void k_zero(float* __restrict__ out) {
    int tid = blockIdx.x * blockDim.x + threadIdx.x;
    int stride = gridDim.x * blockDim.x;
    for (int i = tid; i < NBINS; i += stride) d_hist[i] = 0u;
    for (int i = tid; i < 6 * TOPK_N; i += stride) out[i] = 0.0f;
    for (int i = tid; i < TOPK_N; i += stride) d_valid[i] = 0;
    if (tid < NW) { d_rnz[tid] = 0ull; d_rem1[tid] = 0ull; d_rem2[tid] = 0ull; d_vbw[tid] = 0ull; }
    if (tid == 0) { d_count = 0u; d_spillcount = 0u; d_cutbin = 0u; d_fallback = 0; }
}

// Stream obj: full histogram of s>THR, spill s>0.9 (warp-aggregated).
__global__ void __launch_bounds__(256) k_pass1(const float4* __restrict__ obj4) {
    const int lane = threadIdx.x & 31;
    int tid = blockIdx.x * 256 + threadIdx.x;
    const int gsz = gridDim.x * 256;
    for (int i2 = tid; i2 < NANCH2; i2 += gsz) {
        float4 v = obj4[i2];
        #pragma unroll
        for (int h = 0; h < 2; h++) {
            float l0 = h ? v.z : v.x;
            float l1 = h ? v.w : v.y;
            bool want = false; uint32_t sb = 0;
            if (l1 > l0) {                           // p1 > 0.5
                float s = score_p1_pos(l0, l1);
                sb = __float_as_uint(s);
                uint32_t b = (sb - BITS_BASE) >> 7;
                if (b > (NBINS - 1)) b = NBINS - 1;
                atomicAdd(&d_hist[b], 1u);
                want = (s > SPILL_S);
            }
            unsigned m = __ballot_sync(0xFFFFFFFFu, want);
            if (m) {
                int leader = __ffs(m) - 1;
                uint32_t base = 0;
                if (lane == leader) base = atomicAdd(&d_spillcount, (uint32_t)__popc(m));
                base = __shfl_sync(0xFFFFFFFFu, base, leader);
                if (want) {
                    uint32_t pos = base + __popc(m & ((1u << lane) - 1u));
                    uint32_t idx = 2u * (uint32_t)i2 + (uint32_t)h;
                    if (pos < SPILLCAP) d_spill[pos] = ((ull)sb << 32) | (ull)(~idx);
                }
            }
        }
    }
}

// Smallest bin B with count(bins >= B) >= TOPK_N.
__global__ void k_cutoff() {
    __shared__ uint32_t csum[256], sfine[256];
    __shared__ int s_c;
    __shared__ uint32_t s_acc;
    int t = threadIdx.x;
    int warp = t >> 5, lane = t & 31;
    for (int c = warp; c < 256; c += 8) {
        uint32_t s = 0;
        for (int b = lane; b < 256; b += 32) s += d_hist[c * 256 + b];
        #pragma unroll
        for (int o = 16; o; o >>= 1) s += __shfl_down_sync(0xFFFFFFFFu, s, o);
        if (lane == 0) csum[c] = s;
    }
    __syncthreads();
    if (t == 0) {
        uint32_t acc = 0; int c;
        for (c = 255; c >= 0; c--) {
            if (acc + csum[c] >= TOPK_N) break;
            acc += csum[c];
        }
        s_c = c; s_acc = acc;
    }
    __syncthreads();
    if (s_c >= 0) sfine[t] = d_hist[s_c * 256 + t];
    __syncthreads();
    if (t == 0) {
        uint32_t cut = 0;
        if (s_c >= 0) {
            uint32_t acc = s_acc; int b;
            for (b = 255; b >= 0; b--) {
                acc += sfine[b];
                if (acc >= TOPK_N) break;
            }
            if (b < 0) b = 0;
            cut = (uint32_t)(s_c * 256 + b);
        }
        d_cutbin = cut;
        d_fallback = (cut < PREF_MIN_BIN || d_spillcount > SPILLCAP) ? 1 : 0;
    }
}

// Compact candidates above cutoff: spill fast path, full rescan fallback.
__global__ void __launch_bounds__(256) k_compact(const float4* __restrict__ obj4) {
    uint32_t cut = d_cutbin;
    int tid = blockIdx.x * 256 + threadIdx.x;
    int stride = gridDim.x * 256;
    if (!d_fallback) {
        uint32_t n = d_spillcount; if (n > SPILLCAP) n = SPILLCAP;
        for (uint32_t i = tid; i < n; i += stride) {
            ull key = d_spill[i];
            uint32_t sb = (uint32_t)(key >> 32);
            uint32_t b  = (sb - BITS_BASE) >> 7;
            if (b > (NBINS - 1)) b = NBINS - 1;
            if (b >= cut) {
                uint32_t p = atomicAdd(&d_count, 1u);
                if (p < CAP) d_keys[p] = key;
            }
        }
    } else {
        for (int i2 = tid; i2 < NANCH2; i2 += stride) {
            float4 v = obj4[i2];
            #pragma unroll
            for (int h = 0; h < 2; h++) {
                float l0 = h ? v.z : v.x;
                float l1 = h ? v.w : v.y;
                if (l1 > l0) {
                    float s = score_p1_pos(l0, l1);
                    uint32_t sb = __float_as_uint(s);
                    uint32_t b  = (sb - BITS_BASE) >> 7;
                    if (b > (NBINS - 1)) b = NBINS - 1;
                    if (b >= cut) {
                        uint32_t p = atomicAdd(&d_count, 1u);
                        uint32_t idx = 2u * (uint32_t)i2 + (uint32_t)h;
                        if (p < CAP) d_keys[p] = ((ull)sb << 32) | (ull)(~idx);
                    }
                }
            }
        }
    }
}

// Exact rank (#keys strictly greater; keys unique) fused with box decode.
__global__ void __launch_bounds__(256) k_rankgather(
        const float* __restrict__ obj,
        const float* __restrict__ reg,
        const float* __restrict__ anch,
        float* __restrict__ out) {
    __shared__ ull s_tile[1024];
    int t = threadIdx.x;
    uint32_t cnt = d_count; if (cnt > CAP) cnt = CAP;
    int i = blockIdx.x * 256 + t;
    if (blockIdx.x * 256 >= (int)cnt) return;
    ull mykey = (i < (int)cnt) ? d_keys[i] : 0ull;
    int rank = 0;
    int ntiles = ((int)cnt + 1023) / 1024;
    for (int tb = 0; tb < ntiles; tb++) {
        for (int u = t; u < 1024; u += 256) {
            int j = tb * 1024 + u;
            s_tile[u] = (j < (int)cnt) ? d_keys[j] : 0ull;
        }
        __syncthreads();
        if (i < (int)cnt) {
            int lim = (int)cnt - tb * 1024; if (lim > 1024) lim = 1024;
            for (int u = 0; u < lim; u++) rank += (s_tile[u] > mykey) ? 1 : 0;
        }
        __syncthreads();
    }
    if (i < (int)cnt && rank < TOPK_N) {
        uint32_t idx = ~((uint32_t)mykey);
        float2 l = ((const float2*)obj)[idx];
        float p0, p1;
        if (l.y >= l.x) {
            float x = expf(l.x - l.y);
            float den = x + 1.0f;
            p0 = x / den; p1 = 1.0f / den;
        } else {
            float y = expf(l.y - l.x);
            float den = 1.0f + y;
            p0 = 1.0f / den; p1 = y / den;
        }
        float4 rg = ((const float4*)reg)[idx];
        float4 a  = ((const float4*)anch)[idx];
        float cx = (a.x + a.z * 0.5f) + rg.x * a.z;
        float cy = (a.y + a.w * 0.5f) + rg.y * a.w;
        float w  = a.z * expf(rg.z);
        float h  = a.w * expf(rg.w);
        float bx = cx - w * 0.5f;
        float by = cy - h * 0.5f;
        float x1 = fminf(fmaxf(bx, 0.f), IMGW);
        float y1 = fminf(fmaxf(by, 0.f), IMGH);
        float x2 = fminf(fmaxf(bx + w, 0.f), IMGW);
        float y2 = fminf(fmaxf(by + h, 0.f), IMGH);
        float bw = x2 - x1, bh = y2 - y1;
        out[rank * 4 + 0] = x1;
        out[rank * 4 + 1] = y1;
        out[rank * 4 + 2] = bw;
        out[rank * 4 + 3] = bh;
        out[4 * TOPK_N + rank * 2 + 0] = p0;
        out[4 * TOPK_N + rank * 2 + 1] = p1;
        d_bx1[rank] = x1;
        d_by1[rank] = y1;
        d_bx2[rank] = x1 + bw;
        d_by2[rank] = y1 + bh;
        d_ar[rank]  = bw * bh;
        if (p1 > THR) {
            d_valid[rank] = 1;
            atomicOr(&d_vbw[rank >> 6], 1ull << (rank & 63));
        }
    }
}

// IoU mask matrix; rem1 (pass 1 of sandwich) fused via atomicOr.
__global__ void __launch_bounds__(256) k_mask() {
    __shared__ float s_cx1[4][64], s_cy1[4][64], s_cx2[4][64], s_cy2[4][64], s_ca[4][64];
    const int sub  = threadIdx.x >> 6;
    const int ln   = threadIdx.x & 63;
    const int TT = NW * NW;
    int tile = blockIdx.x * 4 + sub;
    int rb = 0, cb = 0;
    bool tv = tile < TT;
    if (tv) { rb = tile / NW; cb = tile - rb * NW; }
    bool comp = tv && (cb >= rb);
    if (comp) {
        int cj = cb * 64 + ln;
        if (cj < TOPK_N) {
            s_cx1[sub][ln] = d_bx1[cj]; s_cy1[sub][ln] = d_by1[cj];
            s_cx2[sub][ln] = d_bx2[cj]; s_cy2[sub][ln] = d_by2[cj];
            s_ca[sub][ln]  = d_ar[cj];
        }
    }
    __syncthreads();
    if (!tv) return;
    int i = rb * 64 + ln;
    if (i >= TOPK_N) return;
    ull wbits = 0ull;
    if (comp) {
        float x1 = d_bx1[i], y1 = d_by1[i];
        float x2 = d_bx2[i], y2 = d_by2[i], ar = d_ar[i];
        int jmax = TOPK_N - cb * 64; if (jmax > 64) jmax = 64;
        for (int u = 0; u < jmax; u++) {
            int j = cb * 64 + u;
            if (j <= i) continue;
            float iw = fmaxf(fminf(x2, s_cx2[sub][u]) - fmaxf(x1, s_cx1[sub][u]), 0.f);
            float ih = fmaxf(fminf(y2, s_cy2[sub][u]) - fmaxf(y1, s_cy1[sub][u]), 0.f);
            float inter = iw * ih;
            float iou = inter / (ar + s_ca[sub][u] - inter + 1e-8f);
            if (iou > IOU_T) wbits |= (1ull << u);
        }
    }
    d_mask[(size_t)i * NW + cb] = wbits;
    if (wbits && d_valid[i]) {
        atomicOr(&d_rnz[i >> 6], 1ull << (i & 63));
        atomicOr(&d_rem1[cb], wbits);
    }
}

// Pass 2 of sandwich: block c computes rem2[c] = OR of masks[row][c] over
// rows in keep1 (= valid & ~rem1) that are flagged.
__global__ void __launch_bounds__(256) k_rem2() {
    __shared__ int s_rows[TOPK_N > 4096 ? TOPK_N : 4096];
    __shared__ int s_n;
    __shared__ ull s_acc[8];
    int t = threadIdx.x;
    int c = blockIdx.x;
    if (t == 0) s_n = 0;
    __syncthreads();
    if (t < NW) {
        ull bits = d_rnz[t] & ~d_rem1[t];     // keep1 & flagged
        while (bits) {
            int b = __ffsll((long long)bits) - 1;
            bits &= bits - 1ull;
            s_rows[atomicAdd(&s_n, 1)] = t * 64 + b;
        }
    }
    __syncthreads();
    int n = s_n;
    ull acc = 0ull;
    for (int k = t; k < n; k += 256) acc |= d_mask[(size_t)s_rows[k] * NW + c];
    #pragma unroll
    for (int o = 16; o; o >>= 1)
        acc |= __shfl_down_sync(0xFFFFFFFFu, acc, o);
    if ((t & 31) == 0) s_acc[t >> 5] = acc;
    __syncthreads();
    if (t == 0) {
        ull r = 0ull;
        for (int w = 0; w < 8; w++) r |= s_acc[w];
        d_rem2[c] = r;
    }
}

// Final: serial resolution over ambiguous rows only; write keep.
__global__ void k_final(float* __restrict__ out) {
    extern __shared__ ull s_amask[];   // AMAX * NW
    __shared__ ull s_vb[NW], s_rnz[NW], s_rem1[NW], s_rem2[NW], s_amb[NW], s_remv[NW];
    __shared__ int s_alist[AMAX];
    __shared__ int s_apref[NW + 1];
    __shared__ int s_A;
    int t = threadIdx.x;  // 1024

    if (t < NW) {
        s_vb[t]   = d_vbw[t];
        s_rnz[t]  = d_rnz[t];
        s_rem1[t] = d_rem1[t];
        s_rem2[t] = d_rem2[t];
    }
    __syncthreads();
    if (t < NW) s_amb[t] = s_rnz[t] & s_rem1[t] & ~s_rem2[t];
    __syncthreads();
    if (t == 0) {
        int acc = 0;
        for (int w = 0; w < NW; w++) { s_apref[w] = acc; acc += __popcll(s_amb[w]); }
        s_apref[NW] = acc; s_A = acc;
    }
    __syncthreads();
    if (t < NW) {
        ull bits = s_amb[t];
        int slot = s_apref[t];
        while (bits) {
            int b = __ffsll((long long)bits) - 1;
            bits &= bits - 1ull;
            if (slot < AMAX) s_alist[slot] = t * 64 + b;
            slot++;
        }
    }
    __syncthreads();
    int Ac = s_A < AMAX ? s_A : AMAX;
    for (int e = t; e < Ac * NW; e += 1024) {
        int sl = e / NW, c = e - sl * NW;
        s_amask[e] = d_mask[(size_t)s_alist[sl] * NW + c];
    }
    __syncthreads();

    if (t < 32) {
        int l = t;
        ull r0 = s_rem2[l];                          // definite suppressions
        ull r1 = (l + 32 < NW) ? s_rem2[l + 32] : 0ull;
        for (int w = 0; w < NW; w++) {
            if (!s_amb[w]) continue;
            ull v0 = __shfl_sync(0xFFFFFFFFu, r0, w & 31);
            ull v1 = __shfl_sync(0xFFFFFFFFu, r1, w & 31);
            ull remw = (w < 32) ? v0 : v1;
            ull act = s_amb[w] & ~remw;
            while (act) {
                int b = __ffsll((long long)act) - 1;
                act &= act - 1ull;
                int slot = s_apref[w] + __popcll(s_amb[w] & ((1ull << b) - 1ull));
                const ull* src = (slot < AMAX)
                    ? &s_amask[(size_t)slot * NW]
                    : &d_mask[(size_t)(w * 64 + b) * NW];
                r0 |= src[l];
                if (l + 32 < NW) r1 |= src[l + 32];
                act &= ~src[w];
            }
        }
        s_remv[l] = r0;
        if (l + 32 < NW) s_remv[l + 32] = r1;
    }
    __syncthreads();
    for (int i = t; i < TOPK_N; i += 1024) {
        bool kp = ((s_vb[i >> 6] >> (i & 63)) & 1ull) &&
                  !((s_remv[i >> 6] >> (i & 63)) & 1ull);
        out[6 * TOPK_N + i] = kp ? 1.0f : 0.0f;
    }
}

extern "C" void kernel_launch(void* const* d_in, const int* in_sizes, int n_in,
                              void* d_out, int out_size) {
    (void)in_sizes; (void)n_in; (void)out_size;
    const float* obj  = (const float*)d_in[0];
    const float* reg  = (const float*)d_in[1];
    const float* anch = (const float*)d_in[2];
    float* out = (float*)d_out;

    const int FIN_SMEM = AMAX * NW * (int)sizeof(ull);  // 201600
    cudaFuncSetAttribute(k_final, cudaFuncAttributeMaxDynamicSharedMemorySize, FIN_SMEM);

    k_zero      <<<256, 256>>>(out);
    k_pass1     <<<2304, 256>>>((const float4*)obj);
    k_cutoff    <<<1, 256>>>();
    k_compact   <<<512, 256>>>((const float4*)obj);
    k_rankgather<<<CAP / 256, 256>>>(obj, reg, anch, out);
    k_mask      <<<(NW * NW + 3) / 4, 256>>>();
    k_rem2      <<<NW, 256>>>();
    k_final     <<<1, 1024, FIN_SMEM>>>(out);
}

// round 7
// speedup vs baseline: 1.6938x; 1.4801x over previous
#include <cuda_runtime.h>
#include <stdint.h>

// ---------------------------------------------------------------------------
// FasterRCNN RPN proposal head, round 7 = R3 baseline (147.5us) with ONLY the
// NMS replaced by the distributed Jacobi sandwich:
//   k_zero -> k_pass1 (R3-exact: 4608 blocks, shared-stage spill)
//   -> k_cutoff -> k_compact (merged fallback, R3-exact)
//   -> k_rankgather (R3 rank tiles w/ unroll16 + fused box decode)
//   -> k_mask (R3-exact 64-thr blocks; writes all words; fuses rem1/rnz)
//   -> k_rem2 (63 blocks: rem2[c] = OR of keep1-row masks)
//   -> k_final (serial scan over ambiguous rows only)
// ---------------------------------------------------------------------------

#define HF 512
#define WF 512
#define KA 9
#define NANCH (HF * WF * KA)       // 2359296
#define NANCH2 (NANCH / 2)
#define IMGW 16384.0f
#define IMGH 16384.0f
#define TOPK_N 4000
#define THR 0.5f
#define IOU_T 0.3f
#define NW 63
#define NBINS 65536
#define CAP 16384
#define BITS_BASE 0x3F000000u      // bits of 0.5f
#define SPILL_S 0.9f
#define PREF_MIN_BIN 52430u
#define SPILLCAP 400000
#define AMAX 400                   // staged ambiguous rows (400*63*8 = 201600 B)

typedef unsigned long long ull;

// ---- scratch ---------------------------------------------------------------
__device__ uint32_t d_hist[NBINS];
__device__ uint32_t d_cutbin;
__device__ uint32_t d_count;
__device__ uint32_t d_spillcount;
__device__ int      d_fallback;
__device__ ull      d_spill[SPILLCAP];
__device__ ull      d_keys[CAP];
__device__ float d_bx1[TOPK_N], d_by1[TOPK_N], d_bx2[TOPK_N], d_by2[TOPK_N], d_ar[TOPK_N];
__device__ int   d_valid[TOPK_N];
__device__ ull   d_vbw[NW];        // valid bits, packed
__device__ ull   d_mask[TOPK_N * NW];
__device__ ull   d_rnz[NW];        // valid rows with any suppression bit
__device__ ull   d_rem1[NW];       // OR of masks of ALL valid flagged rows
__device__ ull   d_rem2[NW];       // OR of masks of keep1 flagged rows

// p1 of 2-way softmax, bit-identical to jax.nn.softmax (max-side exp == 1.0f).
__device__ __forceinline__ float score_p1_pos(float l0, float l1) {
    float x = expf(l0 - l1);
    return 1.0f / (x + 1.0f);
}

__global__ void k_zero(float* __restrict__ out) {
    int tid = blockIdx.x * blockDim.x + threadIdx.x;
    int stride = gridDim.x * blockDim.x;
    for (int i = tid; i < NBINS; i += stride) d_hist[i] = 0u;
    for (int i = tid; i < 6 * TOPK_N; i += stride) out[i] = 0.0f;
    for (int i = tid; i < TOPK_N; i += stride) {
        d_valid[i] = 0;
        d_bx1[i] = 0.f; d_by1[i] = 0.f; d_bx2[i] = 0.f; d_by2[i] = 0.f; d_ar[i] = 0.f;
    }
    if (tid < NW) { d_rnz[tid] = 0ull; d_rem1[tid] = 0ull; d_rem2[tid] = 0ull; d_vbw[tid] = 0ull; }
    if (tid == 0) { d_count = 0u; d_spillcount = 0u; d_cutbin = 0u; d_fallback = 0; }
}

// R3-exact: one float4 (2 anchors) per thread, shared-stage spill.
__global__ void __launch_bounds__(256) k_pass1(const float4* __restrict__ obj4) {
    __shared__ ull stage[512];
    __shared__ uint32_t s_cnt, s_base;
    int t = threadIdx.x;
    int i2 = blockIdx.x * 256 + t;
    if (t == 0) s_cnt = 0u;
    __syncthreads();
    if (i2 < NANCH2) {
        float4 v = obj4[i2];
        #pragma unroll
        for (int h = 0; h < 2; h++) {
            float l0 = h ? v.z : v.x;
            float l1 = h ? v.w : v.y;
            if (l1 > l0) {                       // p1 > 0.5
                float s = score_p1_pos(l0, l1);
                uint32_t sb = __float_as_uint(s);
                uint32_t b  = (sb - BITS_BASE) >> 7;
                if (b > (NBINS - 1)) b = NBINS - 1;
                atomicAdd(&d_hist[b], 1u);
                if (s > SPILL_S) {
                    uint32_t p = atomicAdd(&s_cnt, 1u);
                    uint32_t idx = 2u * (uint32_t)i2 + (uint32_t)h;
                    stage[p] = ((ull)sb << 32) | (ull)(~idx);
                }
            }
        }
    }
    __syncthreads();
    if (t == 0 && s_cnt) s_base = atomicAdd(&d_spillcount, s_cnt);
    __syncthreads();
    for (int p = t; p < (int)s_cnt; p += 256) {
        uint32_t gp = s_base + p;
        if (gp < SPILLCAP) d_spill[gp] = stage[p];
    }
}

// Smallest bin B with count(bins >= B) >= TOPK_N.
__global__ void k_cutoff() {
    __shared__ uint32_t csum[256], sfine[256];
    __shared__ int s_c;
    __shared__ uint32_t s_acc;
    int t = threadIdx.x;
    int warp = t >> 5, lane = t & 31;
    for (int c = warp; c < 256; c += 8) {
        uint32_t s = 0;
        for (int b = lane; b < 256; b += 32) s += d_hist[c * 256 + b];
        #pragma unroll
        for (int o = 16; o; o >>= 1) s += __shfl_down_sync(0xFFFFFFFFu, s, o);
        if (lane == 0) csum[c] = s;
    }
    __syncthreads();
    if (t == 0) {
        uint32_t acc = 0; int c;
        for (c = 255; c >= 0; c--) {
            if (acc + csum[c] >= TOPK_N) break;
            acc += csum[c];
        }
        s_c = c; s_acc = acc;
    }
    __syncthreads();
    if (s_c >= 0) sfine[t] = d_hist[s_c * 256 + t];
    __syncthreads();
    if (t == 0) {
        uint32_t cut = 0;
        if (s_c >= 0) {
            uint32_t acc = s_acc; int b;
            for (b = 255; b >= 0; b--) {
                acc += sfine[b];
                if (acc >= TOPK_N) break;
            }
            if (b < 0) b = 0;
            cut = (uint32_t)(s_c * 256 + b);
        }
        d_cutbin = cut;
        d_fallback = (cut < PREF_MIN_BIN || d_spillcount > SPILLCAP) ? 1 : 0;
    }
}

// Merged compact: spill fast path / full rescan fallback (R3-exact).
__global__ void __launch_bounds__(256) k_compact(const float4* __restrict__ obj4) {
    uint32_t cut = d_cutbin;
    int stride = gridDim.x * blockDim.x;
    int tid = blockIdx.x * blockDim.x + threadIdx.x;
    if (!d_fallback) {
        uint32_t n = d_spillcount; if (n > SPILLCAP) n = SPILLCAP;
        for (uint32_t i = tid; i < n; i += stride) {
            ull key = d_spill[i];
            uint32_t sb = (uint32_t)(key >> 32);
            uint32_t b  = (sb - BITS_BASE) >> 7;
            if (b > (NBINS - 1)) b = NBINS - 1;
            if (b >= cut) {
                uint32_t p = atomicAdd(&d_count, 1u);
                if (p < CAP) d_keys[p] = key;
            }
        }
    } else {
        for (int i2 = tid; i2 < NANCH2; i2 += stride) {
            float4 v = obj4[i2];
            #pragma unroll
            for (int h = 0; h < 2; h++) {
                float l0 = h ? v.z : v.x;
                float l1 = h ? v.w : v.y;
                if (l1 > l0) {
                    float s = score_p1_pos(l0, l1);
                    uint32_t sb = __float_as_uint(s);
                    uint32_t b  = (sb - BITS_BASE) >> 7;
                    if (b > (NBINS - 1)) b = NBINS - 1;
                    if (b >= cut) {
                        uint32_t p = atomicAdd(&d_count, 1u);
                        uint32_t idx = 2u * (uint32_t)i2 + (uint32_t)h;
                        if (p < CAP) d_keys[p] = ((ull)sb << 32) | (ull)(~idx);
                    }
                }
            }
        }
    }
}

// R3 rank (256-wide tiles, unroll 16) fused with box decode.
__global__ void __launch_bounds__(256) k_rankgather(
        const float* __restrict__ obj,
        const float* __restrict__ reg,
        const float* __restrict__ anch,
        float* __restrict__ out) {
    __shared__ ull tile[256];
    int t = threadIdx.x;
    uint32_t cnt = d_count;
    if (cnt > CAP) cnt = CAP;
    if (blockIdx.x * 256 >= (int)cnt) return;
    int i = blockIdx.x * 256 + t;
    ull mykey = (i < (int)cnt) ? d_keys[i] : 0ull;
    int rank = 0;
    int ntiles = ((int)cnt + 255) / 256;
    for (int tb = 0; tb < ntiles; tb++) {
        int j = tb * 256 + t;
        tile[t] = (j < (int)cnt) ? d_keys[j] : 0ull;
        __syncthreads();
        if (i < (int)cnt) {
#pragma unroll 16
            for (int u = 0; u < 256; u++) rank += (tile[u] > mykey) ? 1 : 0;
        }
        __syncthreads();
    }
    if (i < (int)cnt && rank < TOPK_N) {
        uint32_t idx = ~((uint32_t)mykey);
        float2 l = ((const float2*)obj)[idx];
        float p0, p1;
        if (l.y >= l.x) {
            float x = expf(l.x - l.y);
            float den = x + 1.0f;
            p0 = x / den; p1 = 1.0f / den;
        } else {
            float y = expf(l.y - l.x);
            float den = 1.0f + y;
            p0 = 1.0f / den; p1 = y / den;
        }
        float4 rg = ((const float4*)reg)[idx];
        float4 a  = ((const float4*)anch)[idx];
        float cx = (a.x + a.z * 0.5f) + rg.x * a.z;
        float cy = (a.y + a.w * 0.5f) + rg.y * a.w;
        float w  = a.z * expf(rg.z);
        float h  = a.w * expf(rg.w);
        float bx = cx - w * 0.5f;
        float by = cy - h * 0.5f;
        float x1 = fminf(fmaxf(bx, 0.f), IMGW);
        float y1 = fminf(fmaxf(by, 0.f), IMGH);
        float x2 = fminf(fmaxf(bx + w, 0.f), IMGW);
        float y2 = fminf(fmaxf(by + h, 0.f), IMGH);
        float bw = x2 - x1, bh = y2 - y1;
        out[rank * 4 + 0] = x1;
        out[rank * 4 + 1] = y1;
        out[rank * 4 + 2] = bw;
        out[rank * 4 + 3] = bh;
        out[4 * TOPK_N + rank * 2 + 0] = p0;
        out[4 * TOPK_N + rank * 2 + 1] = p1;
        d_bx1[rank] = x1;
        d_by1[rank] = y1;
        d_bx2[rank] = x1 + bw;
        d_by2[rank] = y1 + bh;
        d_ar[rank]  = bw * bh;
        if (p1 > THR) {
            d_valid[rank] = 1;
            atomicOr(&d_vbw[rank >> 6], 1ull << (rank & 63));
        }
    }
}

// R3-exact tile structure (64-thread blocks); writes every word; fuses
// rnz (valid rows only) and rem1 (pass 1 of sandwich).
__global__ void k_mask() {
    __shared__ float sx1[64], sy1[64], sx2[64], sy2[64], sa[64];
    int cb = blockIdx.x;   // column block
    int rb = blockIdx.y;   // row block
    int t  = threadIdx.x;
    int i  = rb * 64 + t;
    if (cb < rb) {                       // below diagonal: zero word
        if (i < TOPK_N) d_mask[(size_t)i * NW + cb] = 0ull;
        return;
    }
    int cj = cb * 64 + t;
    if (cj < TOPK_N) {
        sx1[t] = d_bx1[cj]; sy1[t] = d_by1[cj];
        sx2[t] = d_bx2[cj]; sy2[t] = d_by2[cj];
        sa[t]  = d_ar[cj];
    }
    __syncthreads();
    if (i >= TOPK_N) return;
    float x1 = d_bx1[i], y1 = d_by1[i], x2 = d_bx2[i], y2 = d_by2[i], ar = d_ar[i];
    ull wbits = 0ull;
    int jmax = TOPK_N - cb * 64;
    if (jmax > 64) jmax = 64;
    for (int u = 0; u < jmax; u++) {
        int j = cb * 64 + u;
        if (j <= i) continue;
        float iw = fmaxf(fminf(x2, sx2[u]) - fmaxf(x1, sx1[u]), 0.f);
        float ih = fmaxf(fminf(y2, sy2[u]) - fmaxf(y1, sy1[u]), 0.f);
        float inter = iw * ih;
        float iou = inter / (ar + sa[u] - inter + 1e-8f);
        if (iou > IOU_T) wbits |= (1ull << u);
    }
    d_mask[(size_t)i * NW + cb] = wbits;
    if (wbits && d_valid[i]) {
        atomicOr(&d_rnz[i >> 6], 1ull << (i & 63));
        atomicOr(&d_rem1[cb], wbits);
    }
}

// Pass 2 of sandwich: block c computes rem2[c] = OR of masks[row][c] over
// keep1 (= valid & ~rem1) flagged rows.
__global__ void __launch_bounds__(256) k_rem2() {
    __shared__ int s_rows[4096];
    __shared__ int s_n;
    __shared__ ull s_acc[8];
    int t = threadIdx.x;
    int c = blockIdx.x;
    if (t == 0) s_n = 0;
    __syncthreads();
    if (t < NW) {
        ull bits = d_rnz[t] & ~d_rem1[t];     // keep1 & flagged
        while (bits) {
            int b = __ffsll((long long)bits) - 1;
            bits &= bits - 1ull;
            s_rows[atomicAdd(&s_n, 1)] = t * 64 + b;
        }
    }
    __syncthreads();
    int n = s_n;
    ull acc = 0ull;
    for (int k = t; k < n; k += 256) acc |= d_mask[(size_t)s_rows[k] * NW + c];
    #pragma unroll
    for (int o = 16; o; o >>= 1)
        acc |= __shfl_down_sync(0xFFFFFFFFu, acc, o);
    if ((t & 31) == 0) s_acc[t >> 5] = acc;
    __syncthreads();
    if (t == 0) {
        ull r = 0ull;
        for (int w = 0; w < 8; w++) r |= s_acc[w];
        d_rem2[c] = r;
    }
}

// Final: serial resolution over ambiguous rows only; write keep.
__global__ void k_final(float* __restrict__ out) {
    extern __shared__ ull s_amask[];   // AMAX * NW
    __shared__ ull s_vb[NW], s_rnz[NW], s_rem1[NW], s_rem2[NW], s_amb[NW], s_remv[NW];
    __shared__ int s_alist[AMAX];
    __shared__ int s_apref[NW + 1];
    __shared__ int s_A;
    int t = threadIdx.x;  // 1024

    if (t < NW) {
        s_vb[t]   = d_vbw[t];
        s_rnz[t]  = d_rnz[t];
        s_rem1[t] = d_rem1[t];
        s_rem2[t] = d_rem2[t];
    }
    __syncthreads();
    if (t < NW) s_amb[t] = s_rnz[t] & s_rem1[t] & ~s_rem2[t];
    __syncthreads();
    if (t == 0) {
        int acc = 0;
        for (int w = 0; w < NW; w++) { s_apref[w] = acc; acc += __popcll(s_amb[w]); }
        s_apref[NW] = acc; s_A = acc;
    }
    __syncthreads();
    if (t < NW) {
        ull bits = s_amb[t];
        int slot = s_apref[t];
        while (bits) {
            int b = __ffsll((long long)bits) - 1;
            bits &= bits - 1ull;
            if (slot < AMAX) s_alist[slot] = t * 64 + b;
            slot++;
        }
    }
    __syncthreads();
    int Ac = s_A < AMAX ? s_A : AMAX;
    for (int e = t; e < Ac * NW; e += 1024) {
        int sl = e / NW, c = e - sl * NW;
        s_amask[e] = d_mask[(size_t)s_alist[sl] * NW + c];
    }
    __syncthreads();

    if (t < 32) {
        int l = t;
        ull r0 = s_rem2[l];                          // definite suppressions
        ull r1 = (l + 32 < NW) ? s_rem2[l + 32] : 0ull;
        for (int w = 0; w < NW; w++) {
            if (!s_amb[w]) continue;
            ull v0 = __shfl_sync(0xFFFFFFFFu, r0, w & 31);
            ull v1 = __shfl_sync(0xFFFFFFFFu, r1, w & 31);
            ull remw = (w < 32) ? v0 : v1;
            ull act = s_amb[w] & ~remw;
            while (act) {
                int b = __ffsll((long long)act) - 1;
                act &= act - 1ull;
                int slot = s_apref[w] + __popcll(s_amb[w] & ((1ull << b) - 1ull));
                const ull* src = (slot < AMAX)
                    ? &s_amask[(size_t)slot * NW]
                    : &d_mask[(size_t)(w * 64 + b) * NW];
                r0 |= src[l];
                if (l + 32 < NW) r1 |= src[l + 32];
                act &= ~src[w];
            }
        }
        s_remv[l] = r0;
        if (l + 32 < NW) s_remv[l + 32] = r1;
    }
    __syncthreads();
    for (int i = t; i < TOPK_N; i += 1024) {
        bool kp = ((s_vb[i >> 6] >> (i & 63)) & 1ull) &&
                  !((s_remv[i >> 6] >> (i & 63)) & 1ull);
        out[6 * TOPK_N + i] = kp ? 1.0f : 0.0f;
    }
}

extern "C" void kernel_launch(void* const* d_in, const int* in_sizes, int n_in,
                              void* d_out, int out_size) {
    (void)in_sizes; (void)n_in; (void)out_size;
    const float* obj  = (const float*)d_in[0];
    const float* reg  = (const float*)d_in[1];
    const float* anch = (const float*)d_in[2];
    float* out = (float*)d_out;

    const int FIN_SMEM = AMAX * NW * (int)sizeof(ull);  // 201600
    cudaFuncSetAttribute(k_final, cudaFuncAttributeMaxDynamicSharedMemorySize, FIN_SMEM);

    k_zero      <<<256, 256>>>(out);
    k_pass1     <<<(NANCH2 + 255) / 256, 256>>>((const float4*)obj);   // 4608
    k_cutoff    <<<1, 256>>>();
    k_compact   <<<512, 256>>>((const float4*)obj);
    k_rankgather<<<CAP / 256, 256>>>(obj, reg, anch, out);
    k_mask      <<<dim3(NW, NW), 64>>>();
    k_rem2      <<<NW, 256>>>();
    k_final     <<<1, 1024, FIN_SMEM>>>(out);
}